// round 8
// baseline (speedup 1.0000x reference)
// SAGNetworkHierarchical GB300 kernel, round 8.
// R7: 389.9 us; gemm 51.7us, fma 40%, issue 61% -> issue-slot bound.
// This round: single change - gemm inner loop converted to packed
// fma.rn.f32x2 (FFMA2), halving FMA instruction count per output.
#include <cuda_runtime.h>
#include <math.h>

#define NN 50000
#define EE 800000
#define HB 65536
#define TCAP 6144

__device__ float    g_hs[NN * 128];
__device__ float    g_hrelu[NN * 128];
__device__ float    g_hs2[NN];
__device__ float    g_score[NN];
__device__ float    g_th[NN];
__device__ unsigned g_key[NN];
__device__ int      g_deg_in[NN];
__device__ int      g_deg_out[NN];
__device__ int      g_rowptr[NN];
__device__ int      g_csr[EE];
__device__ int      g_ord[EE];
__device__ int      g_alive[NN];
__device__ int      g_list[2][NN];
__device__ float    g_ns[NN];
__device__ float    g_nd[NN];
__device__ float    g_mean[128];
__device__ float    g_bmax[3 * 128];
__device__ int      g_total;
__device__ int      g_hist[HB];
__device__ int      g_bucketHi;
__device__ int      g_cntAbove;
__device__ int      g_selcnt;
__device__ int      g_candcnt;
__device__ unsigned g_candk[NN];
__device__ int      g_candv[NN];
__device__ int      g_e1s[EE], g_e1d[EE], g_e1o[EE];
__device__ int      g_e2s[EE], g_e2d[EE], g_e2o[EE];
__device__ int      g_e1n, g_e2n;
__device__ float    g_f1[256];

__device__ __forceinline__ unsigned okey(float f) {
    unsigned u = __float_as_uint(f);
    return (u & 0x80000000u) ? ~u : (u | 0x80000000u);
}
__device__ __forceinline__ void atomicMaxF(float* a, float v) {
    if (v >= 0.f) atomicMax((int*)a, __float_as_int(v));
    else          atomicMin((unsigned*)a, __float_as_uint(v));
}
// packed f32x2 helpers (FFMA2 path; lane-wise identical to scalar fmaf)
__device__ __forceinline__ void ffma2(unsigned long long& d, unsigned long long a,
                                      unsigned long long b) {
    asm("fma.rn.f32x2 %0, %1, %2, %0;" : "+l"(d) : "l"(a), "l"(b));
}
__device__ __forceinline__ unsigned long long pk2(float x) {
    unsigned long long r;
    asm("mov.b64 %0, {%1, %1};" : "=l"(r) : "f"(x));
    return r;
}
__device__ __forceinline__ float2 upk(unsigned long long v) {
    float2 f;
    asm("mov.b64 {%0, %1}, %2;" : "=f"(f.x), "=f"(f.y) : "l"(v));
    return f;
}

__global__ void k_init0() {
    int i = blockIdx.x * blockDim.x + threadIdx.x;
    if (i < NN) { g_alive[i] = 1; g_list[0][i] = i; g_deg_in[i] = 0; g_deg_out[i] = 0; }
    if (i < HB) g_hist[i] = 0;
    if (i < 128) g_mean[i] = 0.f;
    if (i < 3 * 128) g_bmax[i] = __int_as_float(0xff800000);
    if (i == 0) { g_total = 0; g_selcnt = 0; g_candcnt = 0; g_e1n = 0; g_e2n = 0; }
}
__global__ void k_degree0(const int* __restrict__ src, const int* __restrict__ dst) {
    int i = blockIdx.x * blockDim.x + threadIdx.x;
    if (i >= EE) return;
    atomicAdd(&g_deg_out[src[i]], 1);
    g_ord[i] = atomicAdd(&g_deg_in[dst[i]], 1);
}
__global__ void k_degcomp(const int* __restrict__ es, const int* __restrict__ ed, int mode) {
    int i = blockIdx.x * blockDim.x + threadIdx.x;
    int cnt = (mode == 1) ? EE : g_e1n;
    int s = 0, d = 0, od = 0; bool ok = false;
    if (i < cnt) {
        if (mode == 1) { s = es[i]; d = ed[i]; }
        else           { s = g_e1s[i]; d = g_e1d[i]; }
        ok = g_alive[s] && g_alive[d];
    }
    if (ok) { atomicAdd(&g_deg_out[s], 1); od = atomicAdd(&g_deg_in[d], 1); }
    unsigned m = __ballot_sync(~0u, ok);
    if (m) {
        int lane = threadIdx.x & 31;
        int ldr = __ffs(m) - 1;
        int base;
        if (lane == ldr) base = atomicAdd((mode == 1) ? &g_e1n : &g_e2n, __popc(m));
        base = __shfl_sync(~0u, base, ldr);
        if (ok) {
            int p = base + __popc(m & ((1u << lane) - 1));
            if (mode == 1) { g_e1s[p] = s; g_e1d[p] = d; g_e1o[p] = od; }
            else           { g_e2s[p] = s; g_e2d[p] = d; g_e2o[p] = od; }
        }
    }
}
__global__ void k_alloc() {
    int i = blockIdx.x * blockDim.x + threadIdx.x;
    int lane = threadIdx.x & 31;
    int alive = (i < NN) ? g_alive[i] : 0;
    int d = alive ? g_deg_in[i] : 0;
    int x = d;
#pragma unroll
    for (int o = 1; o < 32; o <<= 1) { int t = __shfl_up_sync(~0u, x, o); if (lane >= o) x += t; }
    int base;
    if (lane == 31) base = atomicAdd(&g_total, x);
    base = __shfl_sync(~0u, base, 31);
    if (alive) {
        g_rowptr[i] = base + x - d;
        g_ns[i] = 1.0f / sqrtf(fmaxf((float)g_deg_out[i], 1.0f));
        g_nd[i] = 1.0f / sqrtf(fmaxf((float)d, 1.0f));
    }
}
__global__ void k_scatter(const int* __restrict__ es, const int* __restrict__ ed, int mode) {
    int i = blockIdx.x * blockDim.x + threadIdx.x;
    int cnt = (mode == 0) ? EE : (mode == 1 ? g_e1n : g_e2n);
    if (i >= cnt) return;
    int s, d, od;
    if (mode == 0)      { s = es[i];    d = ed[i];    od = g_ord[i]; }
    else if (mode == 1) { s = g_e1s[i]; d = g_e1d[i]; od = g_e1o[i]; }
    else                { s = g_e2s[i]; d = g_e2d[i]; od = g_e2o[i]; }
    g_csr[g_rowptr[d] + od] = s;
}
// hs[v] = (x[v] @ W) * ns[v] * (useTh ? th[v] : 1); x==null means g_hrelu.
// Inner loop in packed f32x2: per (row, 4k): 1 LDS.128 + 4 packs + 8 FFMA2.
__global__ __launch_bounds__(256, 3) void k_gemm(const float* __restrict__ x,
                                                 const float* __restrict__ W,
                                                 int lin, int nA, int useTh) {
    __shared__ float xs[64][128];
    __shared__ int rid[64];
    const float* xp = x ? x : (const float*)g_hrelu;
    int tid = threadIdx.x;
    if (tid < 64) {
        int r = blockIdx.x * 64 + tid;
        rid[tid] = (r < nA) ? g_list[lin][r] : -1;
    }
    __syncthreads();
    for (int i = tid; i < 2048; i += 256) {
        int row = i >> 5, c4 = i & 31;
        int v = rid[row];
        float4 xv = make_float4(0.f, 0.f, 0.f, 0.f);
        if (v >= 0) xv = *(const float4*)&xp[v * 128 + c4 * 4];
        *(float4*)&xs[row][c4 * 4] = xv;
    }
    __syncthreads();
    int cg = tid & 31, rg = tid >> 5;
    unsigned long long aA[8], aB[8];
#pragma unroll
    for (int j = 0; j < 8; j++) { aA[j] = 0ull; aB[j] = 0ull; }
#pragma unroll 8
    for (int k0 = 0; k0 < 128; k0 += 4) {
        ulonglong2 w0 = *(const ulonglong2*)&W[(k0 + 0) * 128 + cg * 4];
        ulonglong2 w1 = *(const ulonglong2*)&W[(k0 + 1) * 128 + cg * 4];
        ulonglong2 w2 = *(const ulonglong2*)&W[(k0 + 2) * 128 + cg * 4];
        ulonglong2 w3 = *(const ulonglong2*)&W[(k0 + 3) * 128 + cg * 4];
#pragma unroll
        for (int j = 0; j < 8; j++) {
            float4 xv = *(const float4*)&xs[rg * 8 + j][k0];
            unsigned long long xx;
            xx = pk2(xv.x); ffma2(aA[j], xx, w0.x); ffma2(aB[j], xx, w0.y);
            xx = pk2(xv.y); ffma2(aA[j], xx, w1.x); ffma2(aB[j], xx, w1.y);
            xx = pk2(xv.z); ffma2(aA[j], xx, w2.x); ffma2(aB[j], xx, w2.y);
            xx = pk2(xv.w); ffma2(aA[j], xx, w3.x); ffma2(aB[j], xx, w3.y);
        }
    }
#pragma unroll
    for (int j = 0; j < 8; j++) {
        int v = rid[rg * 8 + j];
        if (v >= 0) {
            float s = g_ns[v] * (useTh ? g_th[v] : 1.0f);
            float2 lo = upk(aA[j]), hi = upk(aB[j]);
            float4 o = make_float4(lo.x * s, lo.y * s, hi.x * s, hi.y * s);
            *(float4*)&g_hs[v * 128 + cg * 4] = o;
        }
    }
}
__global__ __launch_bounds__(256) void k_spmm_conv(const float* __restrict__ cb,
                                                   const float* __restrict__ sW,
                                                   int lin, int nA) {
    int gw = (blockIdx.x * blockDim.x + threadIdx.x) >> 5;
    int lane = threadIdx.x & 31;
    if (gw >= nA) return;
    int v = g_list[lin][gw];
    int s = g_rowptr[v];
    int nb = g_deg_in[v];
    float a0 = 0.f, a1 = 0.f, a2 = 0.f, a3 = 0.f;
    for (int i0 = 0; i0 < nb; i0 += 32) {
        int u32 = (i0 + lane < nb) ? g_csr[s + i0 + lane] : 0;
        int lim = min(32, nb - i0);
        for (int j = 0; j < lim; j++) {
            int u = __shfl_sync(~0u, u32, j);
            float4 h = *(const float4*)&g_hs[u * 128 + lane * 4];
            a0 += h.x; a1 += h.y; a2 += h.z; a3 += h.w;
        }
    }
    float ndv = g_nd[v];
    float4 b = *(const float4*)&cb[lane * 4];
    float4 hr;
    hr.x = fmaxf(fmaf(a0, ndv, b.x), 0.f);
    hr.y = fmaxf(fmaf(a1, ndv, b.y), 0.f);
    hr.z = fmaxf(fmaf(a2, ndv, b.z), 0.f);
    hr.w = fmaxf(fmaf(a3, ndv, b.w), 0.f);
    *(float4*)&g_hrelu[v * 128 + lane * 4] = hr;
    float4 w = *(const float4*)&sW[lane * 4];
    float sd = hr.x * w.x + hr.y * w.y + hr.z * w.z + hr.w * w.w;
#pragma unroll
    for (int o = 16; o; o >>= 1) sd += __shfl_down_sync(~0u, sd, o);
    if (lane == 0) g_hs2[v] = sd * g_ns[v];
}
__global__ __launch_bounds__(256) void k_spmm_score(const float* __restrict__ sb,
                                                    int lin, int nA) {
    int gw = (blockIdx.x * blockDim.x + threadIdx.x) >> 5;
    int lane = threadIdx.x & 31;
    if (gw >= nA) return;
    int v = g_list[lin][gw];
    int s = g_rowptr[v], e = s + g_deg_in[v];
    float sum = 0.f;
    for (int i = s + lane; i < e; i += 32) sum += g_hs2[g_csr[i]];
#pragma unroll
    for (int o = 16; o; o >>= 1) sum += __shfl_down_sync(~0u, sum, o);
    if (lane == 0) {
        float sc = fmaf(sum, g_nd[v], sb[0]);
        g_score[v] = sc;
        unsigned kk = okey(sc);
        g_key[v] = kk;
        atomicAdd(&g_hist[kk >> 16], 1);
    }
}
__global__ __launch_bounds__(1024) void k_pick(int k) {
    __shared__ int A[1024];
    int t = threadIdx.x;
    const int4* h4 = (const int4*)g_hist;
    int base4 = t * 16;
    int s = 0;
#pragma unroll
    for (int b = 0; b < 16; b++) {
        int4 v = h4[base4 + b];
        s += v.x + v.y + v.z + v.w;
    }
    A[t] = s;
    __syncthreads();
    for (int off = 1; off < 1024; off <<= 1) {
        int w = A[t] + ((t + off < 1024) ? A[t + off] : 0);
        __syncthreads();
        A[t] = w;
        __syncthreads();
    }
    int above = A[t] - s;
    if (above < k && above + s >= k) {
        int cum = above;
        int base = t * 64;
        for (int b = 63; b >= 0; b--) {
            int h = g_hist[base + b];
            if (cum + h >= k) { g_bucketHi = base + b; g_cntAbove = cum; break; }
            cum += h;
        }
    }
}
__global__ void k_cand(int lin, int lout, int nA) {
    int i = blockIdx.x * blockDim.x + threadIdx.x;
    int bh = g_bucketHi;
    int v = -1; unsigned key = 0; int hi = -1;
    if (i < nA) { v = g_list[lin][i]; key = g_key[v]; hi = (int)(key >> 16); }
    bool gt = (i < nA) && (hi > bh);
    bool eq = (i < nA) && (hi == bh);
    int lane = threadIdx.x & 31;
    unsigned m = __ballot_sync(~0u, gt);
    if (m) {
        int ldr = __ffs(m) - 1; int base;
        if (lane == ldr) base = atomicAdd(&g_selcnt, __popc(m));
        base = __shfl_sync(~0u, base, ldr);
        if (gt) g_list[lout][base + __popc(m & ((1u << lane) - 1))] = v;
    }
    unsigned m2 = __ballot_sync(~0u, eq);
    if (m2) {
        int ldr = __ffs(m2) - 1; int base;
        if (lane == ldr) base = atomicAdd(&g_candcnt, __popc(m2));
        base = __shfl_sync(~0u, base, ldr);
        if (eq) {
            int p = base + __popc(m2 & ((1u << lane) - 1));
            g_candk[p] = key; g_candv[p] = v;
        }
    }
    if (i < nA && !gt && !eq) g_alive[v] = 0;
}
__global__ __launch_bounds__(1024) void k_finish(int lout, int k) {
    __shared__ int hist[256];
    __shared__ int sh_b1, sh_rem1, sh_b0, sh_needed, sh_tc;
    __shared__ int tiebuf[TCAP];
    int tid = threadIdx.x;
    int C = g_candcnt;
    int kp = k - g_cntAbove;
    for (int i = tid; i < 256; i += 1024) hist[i] = 0;
    if (tid == 0) sh_tc = 0;
    __syncthreads();
    for (int i = tid; i < C; i += 1024) atomicAdd(&hist[(g_candk[i] >> 8) & 255], 1);
    __syncthreads();
    if (tid == 0) {
        int cum = 0;
        for (int b = 255; b >= 0; b--) {
            int h = hist[b];
            if (cum + h >= kp) { sh_b1 = b; sh_rem1 = kp - cum; break; }
            cum += h;
        }
    }
    __syncthreads();
    int b1 = sh_b1, rem1 = sh_rem1;
    for (int i = tid; i < 256; i += 1024) hist[i] = 0;
    __syncthreads();
    for (int i = tid; i < C; i += 1024) {
        unsigned kk = g_candk[i];
        if ((int)((kk >> 8) & 255) == b1) atomicAdd(&hist[kk & 255], 1);
    }
    __syncthreads();
    if (tid == 0) {
        int cum = 0;
        for (int b = 255; b >= 0; b--) {
            int h = hist[b];
            if (cum + h >= rem1) { sh_b0 = b; sh_needed = rem1 - cum; break; }
            cum += h;
        }
    }
    __syncthreads();
    unsigned lo_t = ((unsigned)b1 << 8) | (unsigned)sh_b0;
    int needed = sh_needed;
    for (int i = tid; i < C; i += 1024) {
        unsigned lo = g_candk[i] & 0xFFFFu;
        int v = g_candv[i];
        if (lo > lo_t) {
            int p = atomicAdd(&g_selcnt, 1);
            g_list[lout][p] = v;
        } else if (lo < lo_t) {
            g_alive[v] = 0;
        } else {
            int p = atomicAdd(&sh_tc, 1);
            if (p < TCAP) tiebuf[p] = v;
        }
    }
    __syncthreads();
    int T = sh_tc;
    if (T <= needed) {
        for (int i = tid; i < C; i += 1024) {
            if ((g_candk[i] & 0xFFFFu) == lo_t) {
                int p = atomicAdd(&g_selcnt, 1);
                g_list[lout][p] = g_candv[i];
            }
        }
    } else if (T <= TCAP) {
        for (int j = tid; j < T; j += 1024) {
            int vj = tiebuf[j];
            int r = 0;
            for (int q = 0; q < T; q++) r += (tiebuf[q] < vj);
            if (r < needed) {
                int p = atomicAdd(&g_selcnt, 1);
                g_list[lout][p] = vj;
            } else g_alive[vj] = 0;
        }
    } else {
        for (int i = tid; i < C; i += 1024) {
            if ((g_candk[i] & 0xFFFFu) != lo_t) continue;
            int vi = g_candv[i];
            int r = 0;
            for (int q = 0; q < C; q++)
                if ((g_candk[q] & 0xFFFFu) == lo_t && g_candv[q] < vi) r++;
            if (r < needed) {
                int p = atomicAdd(&g_selcnt, 1);
                g_list[lout][p] = vi;
            } else g_alive[vi] = 0;
        }
    }
}
__global__ __launch_bounds__(128) void k_pool(int b, int lout, int kb, float invk, int doZero) {
    __shared__ float sth[64];
    __shared__ int sv[64];
    int c = threadIdx.x;
    int base = blockIdx.x * 64;
    int lim = min(64, kb - base);
    if (c < 64 && c < lim) {
        int v = g_list[lout][base + c];
        float th = tanhf(g_score[v]);
        sth[c] = th; sv[c] = v; g_th[v] = th;
        if (doZero) { g_deg_in[v] = 0; g_deg_out[v] = 0; }
    }
    if (doZero) {
        for (int i = blockIdx.x * blockDim.x + c; i < HB; i += gridDim.x * blockDim.x) g_hist[i] = 0;
        if (base == 0 && c == 0) {
            g_total = 0; g_selcnt = 0; g_candcnt = 0;
            if (b == 0) g_e1n = 0; else g_e2n = 0;
        }
    }
    __syncthreads();
    float msum = 0.f, mmax = __int_as_float(0xff800000);
    for (int j = 0; j < lim; j++) {
        float val = g_hrelu[sv[j] * 128 + c] * sth[j];
        msum += val;
        mmax = fmaxf(mmax, val);
    }
    atomicAdd(&g_mean[c], msum * invk);
    atomicMaxF(&g_bmax[b * 128 + c], mmax);
}
__global__ __launch_bounds__(1024) void k_lin1(const float* __restrict__ seq,
                                               const float* __restrict__ W,
                                               const float* __restrict__ b) {
    __shared__ float fin[1280];
    __shared__ float red[1024];
    int t = threadIdx.x;
    for (int i = t; i < 1280; i += 1024) {
        float v;
        if (i < 128)      v = g_mean[i];
        else if (i < 256) v = g_bmax[i - 128] + g_bmax[128 + (i - 128)] + g_bmax[256 + (i - 128)];
        else              v = seq[i - 256];
        fin[i] = v;
    }
    __syncthreads();
    int o = t & 255, part = t >> 8;
    float acc = 0.f;
    int k0 = part * 320;
    for (int k = k0; k < k0 + 320; k++) acc = fmaf(fin[k], W[k * 256 + o], acc);
    red[t] = acc;
    __syncthreads();
    if (t < 256) {
        float s = red[t] + red[t + 256] + red[t + 512] + red[t + 768] + b[t];
        g_f1[t] = fmaxf(s, 0.f);
    }
}
__global__ __launch_bounds__(1024) void k_lin23(const float* __restrict__ W2, const float* __restrict__ b2,
                                                const float* __restrict__ W3, const float* __restrict__ b3,
                                                float* __restrict__ out) {
    __shared__ float f1[256];
    __shared__ float f2[128];
    int t = threadIdx.x;
    if (t < 256) f1[t] = g_f1[t];
    __syncthreads();
    if (t < 128) {
        float acc = b2[t];
        for (int k = 0; k < 256; k++) acc = fmaf(f1[k], W2[k * 128 + t], acc);
        f2[t] = fmaxf(acc, 0.f);
    }
    __syncthreads();
#pragma unroll
    for (int r = 0; r < 2; r++) {
        int o = t + r * 1024;
        float acc = b3[o];
        for (int k = 0; k < 128; k++) acc = fmaf(f2[k], W3[k * 2048 + o], acc);
        out[o] = acc;
    }
}

extern "C" void kernel_launch(void* const* d_in, const int* in_sizes, int n_in,
                              void* d_out, int out_size) {
    const float* feat = (const float*)d_in[0];
    const float* seq  = (const float*)d_in[1];
    const int*   src  = (const int*)d_in[2];
    const int*   dst  = (const int*)d_in[3];
    const float* cW[3] = {(const float*)d_in[6],  (const float*)d_in[10], (const float*)d_in[14]};
    const float* cb[3] = {(const float*)d_in[7],  (const float*)d_in[11], (const float*)d_in[15]};
    const float* sW[3] = {(const float*)d_in[8],  (const float*)d_in[12], (const float*)d_in[16]};
    const float* sb[3] = {(const float*)d_in[9],  (const float*)d_in[13], (const float*)d_in[17]};
    const float* l1W = (const float*)d_in[18];
    const float* l1b = (const float*)d_in[19];
    const float* l2W = (const float*)d_in[20];
    const float* l2b = (const float*)d_in[21];
    const float* l3W = (const float*)d_in[22];
    const float* l3b = (const float*)d_in[23];
    float* out = (float*)d_out;

    const int nAv[3] = {50000, 25000, 12500};
    const int kbv[3] = {25000, 12500, 6250};
    const int EGRID = (EE + 255) / 256;

    k_init0<<<(HB + 255) / 256, 256>>>();
    for (int b = 0; b < 3; b++) {
        int nA = nAv[b], kb = kbv[b];
        int lin = b & 1, lout = 1 - lin;
        if (b == 0) k_degree0<<<EGRID, 256>>>(src, dst);
        else        k_degcomp<<<EGRID, 256>>>(src, dst, b);
        k_alloc<<<(NN + 255) / 256, 256>>>();
        k_gemm<<<(nA + 63) / 64, 256>>>(b == 0 ? feat : (const float*)0, cW[b], lin, nA, b > 0);
        k_scatter<<<EGRID, 256>>>(src, dst, b);
        k_spmm_conv<<<(nA + 7) / 8, 256>>>(cb[b], sW[b], lin, nA);
        k_spmm_score<<<(nA + 7) / 8, 256>>>(sb[b], lin, nA);
        k_pick<<<1, 1024>>>(kb);
        k_cand<<<(nA + 255) / 256, 256>>>(lin, lout, nA);
        k_finish<<<1, 1024>>>(lout, kb);
        k_pool<<<(kb + 63) / 64, 128>>>(b, lout, kb, 1.0f / (float)kb, b < 2);
    }
    k_lin1<<<1, 1024>>>(seq, l1W, l1b);
    k_lin23<<<1, 1024>>>(l2W, l2b, l3W, l3b, out);
}

// round 10
// speedup vs baseline: 1.0828x; 1.0828x over previous
// SAGNetworkHierarchical GB300 kernel, round 10.
// R9 fusion failed determinism: gemm epilogue read g_ns BEFORE k_alloc wrote
// it. Fix: gemm writes raw (x@W)*th; ns[u] applied per-neighbor inside the
// SpMM gather (shfl-broadcast with the index). Fusion retained.
#include <cuda_runtime.h>
#include <math.h>

#define NN 50000
#define EE 800000
#define HB 65536
#define TCAP 6144

__device__ float    g_hs[NN * 128];
__device__ float    g_hrelu[NN * 128];
__device__ float    g_hs2[NN];
__device__ float    g_score[NN];
__device__ float    g_th[NN];
__device__ unsigned g_key[NN];
__device__ int      g_deg_in[NN];
__device__ int      g_deg_out[NN];
__device__ int      g_rowptr[NN];
__device__ int      g_csr[EE];
__device__ int      g_ord[EE];
__device__ int      g_alive[NN];
__device__ int      g_list[2][NN];
__device__ float    g_ns[NN];
__device__ float    g_nd[NN];
__device__ float    g_mean[128];
__device__ float    g_bmax[3 * 128];
__device__ int      g_total;
__device__ int      g_hist[HB];
__device__ int      g_bucketHi;
__device__ int      g_cntAbove;
__device__ int      g_selcnt;
__device__ int      g_candcnt;
__device__ unsigned g_candk[NN];
__device__ int      g_candv[NN];
__device__ int      g_e1s[EE], g_e1d[EE], g_e1o[EE];
__device__ int      g_e2s[EE], g_e2d[EE], g_e2o[EE];
__device__ int      g_e1n, g_e2n;

__device__ __forceinline__ unsigned okey(float f) {
    unsigned u = __float_as_uint(f);
    return (u & 0x80000000u) ? ~u : (u | 0x80000000u);
}
__device__ __forceinline__ void atomicMaxF(float* a, float v) {
    if (v >= 0.f) atomicMax((int*)a, __float_as_int(v));
    else          atomicMin((unsigned*)a, __float_as_uint(v));
}

__global__ void k_init0() {
    int i = blockIdx.x * blockDim.x + threadIdx.x;
    if (i < NN) { g_alive[i] = 1; g_list[0][i] = i; g_deg_in[i] = 0; g_deg_out[i] = 0; }
    if (i < HB) g_hist[i] = 0;
    if (i < 128) g_mean[i] = 0.f;
    if (i < 3 * 128) g_bmax[i] = __int_as_float(0xff800000);
    if (i == 0) { g_total = 0; g_selcnt = 0; g_candcnt = 0; g_e1n = 0; g_e2n = 0; }
}
// Fused: blocks [0,gemmBlocks) = dense x@W tile (NO current-block state read:
// output is raw (x@W)*th); blocks beyond = degree counting / edge compaction.
__global__ __launch_bounds__(256, 3) void k_deg_gemm(
    const float* __restrict__ x, const float* __restrict__ W,
    int lin, int nA, int useTh,
    const int* __restrict__ es, const int* __restrict__ ed, int mode,
    int gemmBlocks) {
    __shared__ float xs[64][128];
    __shared__ int rid[64];
    int tid = threadIdx.x;
    if (blockIdx.x >= gemmBlocks) {
        int i = (blockIdx.x - gemmBlocks) * 256 + tid;
        if (mode == 0) {
            if (i < EE) {
                atomicAdd(&g_deg_out[es[i]], 1);
                g_ord[i] = atomicAdd(&g_deg_in[ed[i]], 1);
            }
            return;
        }
        int cnt = (mode == 1) ? EE : g_e1n;
        int s = 0, d = 0, od = 0; bool ok = false;
        if (i < cnt) {
            if (mode == 1) { s = es[i]; d = ed[i]; }
            else           { s = g_e1s[i]; d = g_e1d[i]; }
            ok = g_alive[s] && g_alive[d];
        }
        if (ok) { atomicAdd(&g_deg_out[s], 1); od = atomicAdd(&g_deg_in[d], 1); }
        unsigned m = __ballot_sync(~0u, ok);
        if (m) {
            int lane = tid & 31;
            int ldr = __ffs(m) - 1;
            int base;
            if (lane == ldr) base = atomicAdd((mode == 1) ? &g_e1n : &g_e2n, __popc(m));
            base = __shfl_sync(~0u, base, ldr);
            if (ok) {
                int p = base + __popc(m & ((1u << lane) - 1));
                if (mode == 1) { g_e1s[p] = s; g_e1d[p] = d; g_e1o[p] = od; }
                else           { g_e2s[p] = s; g_e2d[p] = d; g_e2o[p] = od; }
            }
        }
        return;
    }
    const float* xp = x ? x : (const float*)g_hrelu;
    if (tid < 64) {
        int r = blockIdx.x * 64 + tid;
        rid[tid] = (r < nA) ? g_list[lin][r] : -1;
    }
    __syncthreads();
    for (int i = tid; i < 2048; i += 256) {
        int row = i >> 5, c4 = i & 31;
        int v = rid[row];
        float4 xv = make_float4(0.f, 0.f, 0.f, 0.f);
        if (v >= 0) xv = *(const float4*)&xp[v * 128 + c4 * 4];
        *(float4*)&xs[row][c4 * 4] = xv;
    }
    __syncthreads();
    int cg = tid & 31, rg = tid >> 5;
    float4 acc[8];
#pragma unroll
    for (int j = 0; j < 8; j++) acc[j] = make_float4(0.f, 0.f, 0.f, 0.f);
#pragma unroll 8
    for (int k0 = 0; k0 < 128; k0 += 4) {
        float4 w0 = *(const float4*)&W[(k0 + 0) * 128 + cg * 4];
        float4 w1 = *(const float4*)&W[(k0 + 1) * 128 + cg * 4];
        float4 w2 = *(const float4*)&W[(k0 + 2) * 128 + cg * 4];
        float4 w3 = *(const float4*)&W[(k0 + 3) * 128 + cg * 4];
#pragma unroll
        for (int j = 0; j < 8; j++) {
            float4 xv = *(const float4*)&xs[rg * 8 + j][k0];
            acc[j].x = fmaf(xv.x, w0.x, acc[j].x); acc[j].y = fmaf(xv.x, w0.y, acc[j].y);
            acc[j].z = fmaf(xv.x, w0.z, acc[j].z); acc[j].w = fmaf(xv.x, w0.w, acc[j].w);
            acc[j].x = fmaf(xv.y, w1.x, acc[j].x); acc[j].y = fmaf(xv.y, w1.y, acc[j].y);
            acc[j].z = fmaf(xv.y, w1.z, acc[j].z); acc[j].w = fmaf(xv.y, w1.w, acc[j].w);
            acc[j].x = fmaf(xv.z, w2.x, acc[j].x); acc[j].y = fmaf(xv.z, w2.y, acc[j].y);
            acc[j].z = fmaf(xv.z, w2.z, acc[j].z); acc[j].w = fmaf(xv.z, w2.w, acc[j].w);
            acc[j].x = fmaf(xv.w, w3.x, acc[j].x); acc[j].y = fmaf(xv.w, w3.y, acc[j].y);
            acc[j].z = fmaf(xv.w, w3.z, acc[j].z); acc[j].w = fmaf(xv.w, w3.w, acc[j].w);
        }
    }
#pragma unroll
    for (int j = 0; j < 8; j++) {
        int v = rid[rg * 8 + j];
        if (v >= 0) {
            float s = useTh ? g_th[v] : 1.0f;   // th from PREVIOUS block: safe
            float4 o = make_float4(acc[j].x * s, acc[j].y * s, acc[j].z * s, acc[j].w * s);
            *(float4*)&g_hs[v * 128 + cg * 4] = o;
        }
    }
}
__global__ void k_alloc() {
    int i = blockIdx.x * blockDim.x + threadIdx.x;
    int lane = threadIdx.x & 31;
    int alive = (i < NN) ? g_alive[i] : 0;
    int d = alive ? g_deg_in[i] : 0;
    int x = d;
#pragma unroll
    for (int o = 1; o < 32; o <<= 1) { int t = __shfl_up_sync(~0u, x, o); if (lane >= o) x += t; }
    int base;
    if (lane == 31) base = atomicAdd(&g_total, x);
    base = __shfl_sync(~0u, base, 31);
    if (alive) {
        g_rowptr[i] = base + x - d;
        g_ns[i] = 1.0f / sqrtf(fmaxf((float)g_deg_out[i], 1.0f));
        g_nd[i] = 1.0f / sqrtf(fmaxf((float)d, 1.0f));
    }
}
__global__ void k_scatter(const int* __restrict__ es, const int* __restrict__ ed, int mode) {
    int i = blockIdx.x * blockDim.x + threadIdx.x;
    int cnt = (mode == 0) ? EE : (mode == 1 ? g_e1n : g_e2n);
    if (i >= cnt) return;
    int s, d, od;
    if (mode == 0)      { s = es[i];    d = ed[i];    od = g_ord[i]; }
    else if (mode == 1) { s = g_e1s[i]; d = g_e1d[i]; od = g_e1o[i]; }
    else                { s = g_e2s[i]; d = g_e2d[i]; od = g_e2o[i]; }
    g_csr[g_rowptr[d] + od] = s;
}
// gather-SpMM; ns[u] applied per neighbor (hs is raw (x@W)*th now)
__global__ __launch_bounds__(256) void k_spmm_conv(const float* __restrict__ cb,
                                                   const float* __restrict__ sW,
                                                   int lin, int nA) {
    int gw = (blockIdx.x * blockDim.x + threadIdx.x) >> 5;
    int lane = threadIdx.x & 31;
    if (gw >= nA) return;
    int v = g_list[lin][gw];
    int s = g_rowptr[v];
    int nb = g_deg_in[v];
    float a0 = 0.f, a1 = 0.f, a2 = 0.f, a3 = 0.f;
    for (int i0 = 0; i0 < nb; i0 += 32) {
        int u32 = 0; float ns32 = 0.f;
        if (i0 + lane < nb) { u32 = g_csr[s + i0 + lane]; ns32 = g_ns[u32]; }
        int lim = min(32, nb - i0);
        for (int j = 0; j < lim; j++) {
            int u = __shfl_sync(~0u, u32, j);
            float nsu = __shfl_sync(~0u, ns32, j);
            float4 h = *(const float4*)&g_hs[u * 128 + lane * 4];
            a0 = fmaf(h.x, nsu, a0); a1 = fmaf(h.y, nsu, a1);
            a2 = fmaf(h.z, nsu, a2); a3 = fmaf(h.w, nsu, a3);
        }
    }
    float ndv = g_nd[v];
    float4 b = *(const float4*)&cb[lane * 4];
    float4 hr;
    hr.x = fmaxf(fmaf(a0, ndv, b.x), 0.f);
    hr.y = fmaxf(fmaf(a1, ndv, b.y), 0.f);
    hr.z = fmaxf(fmaf(a2, ndv, b.z), 0.f);
    hr.w = fmaxf(fmaf(a3, ndv, b.w), 0.f);
    *(float4*)&g_hrelu[v * 128 + lane * 4] = hr;
    float4 w = *(const float4*)&sW[lane * 4];
    float sd = hr.x * w.x + hr.y * w.y + hr.z * w.z + hr.w * w.w;
#pragma unroll
    for (int o = 16; o; o >>= 1) sd += __shfl_down_sync(~0u, sd, o);
    if (lane == 0) g_hs2[v] = sd * g_ns[v];
}
__global__ __launch_bounds__(256) void k_spmm_score(const float* __restrict__ sb,
                                                    int lin, int nA) {
    int gw = (blockIdx.x * blockDim.x + threadIdx.x) >> 5;
    int lane = threadIdx.x & 31;
    if (gw >= nA) return;
    int v = g_list[lin][gw];
    int s = g_rowptr[v], e = s + g_deg_in[v];
    float sum = 0.f;
    for (int i = s + lane; i < e; i += 32) sum += g_hs2[g_csr[i]];
#pragma unroll
    for (int o = 16; o; o >>= 1) sum += __shfl_down_sync(~0u, sum, o);
    if (lane == 0) {
        float sc = fmaf(sum, g_nd[v], sb[0]);
        g_score[v] = sc;
        unsigned kk = okey(sc);
        g_key[v] = kk;
        atomicAdd(&g_hist[kk >> 16], 1);
    }
}
__global__ __launch_bounds__(1024) void k_pick(int k) {
    __shared__ int A[1024];
    int t = threadIdx.x;
    const int4* h4 = (const int4*)g_hist;
    int base4 = t * 16;
    int s = 0;
#pragma unroll
    for (int b = 0; b < 16; b++) {
        int4 v = h4[base4 + b];
        s += v.x + v.y + v.z + v.w;
    }
    A[t] = s;
    __syncthreads();
    for (int off = 1; off < 1024; off <<= 1) {
        int w = A[t] + ((t + off < 1024) ? A[t + off] : 0);
        __syncthreads();
        A[t] = w;
        __syncthreads();
    }
    int above = A[t] - s;
    if (above < k && above + s >= k) {
        int cum = above;
        int base = t * 64;
        for (int b = 63; b >= 0; b--) {
            int h = g_hist[base + b];
            if (cum + h >= k) { g_bucketHi = base + b; g_cntAbove = cum; break; }
            cum += h;
        }
    }
}
__global__ void k_cand(int lin, int lout, int nA) {
    int i = blockIdx.x * blockDim.x + threadIdx.x;
    int bh = g_bucketHi;
    int v = -1; unsigned key = 0; int hi = -1;
    if (i < nA) { v = g_list[lin][i]; key = g_key[v]; hi = (int)(key >> 16); }
    bool gt = (i < nA) && (hi > bh);
    bool eq = (i < nA) && (hi == bh);
    int lane = threadIdx.x & 31;
    unsigned m = __ballot_sync(~0u, gt);
    if (m) {
        int ldr = __ffs(m) - 1; int base;
        if (lane == ldr) base = atomicAdd(&g_selcnt, __popc(m));
        base = __shfl_sync(~0u, base, ldr);
        if (gt) g_list[lout][base + __popc(m & ((1u << lane) - 1))] = v;
    }
    unsigned m2 = __ballot_sync(~0u, eq);
    if (m2) {
        int ldr = __ffs(m2) - 1; int base;
        if (lane == ldr) base = atomicAdd(&g_candcnt, __popc(m2));
        base = __shfl_sync(~0u, base, ldr);
        if (eq) {
            int p = base + __popc(m2 & ((1u << lane) - 1));
            g_candk[p] = key; g_candv[p] = v;
        }
    }
    if (i < nA && !gt && !eq) g_alive[v] = 0;
}
__global__ __launch_bounds__(1024) void k_finish(int lout, int k) {
    __shared__ int hist[256];
    __shared__ int sh_b1, sh_rem1, sh_b0, sh_needed, sh_tc;
    __shared__ int tiebuf[TCAP];
    int tid = threadIdx.x;
    int C = g_candcnt;
    int kp = k - g_cntAbove;
    for (int i = tid; i < 256; i += 1024) hist[i] = 0;
    if (tid == 0) sh_tc = 0;
    __syncthreads();
    for (int i = tid; i < C; i += 1024) atomicAdd(&hist[(g_candk[i] >> 8) & 255], 1);
    __syncthreads();
    if (tid == 0) {
        int cum = 0;
        for (int b = 255; b >= 0; b--) {
            int h = hist[b];
            if (cum + h >= kp) { sh_b1 = b; sh_rem1 = kp - cum; break; }
            cum += h;
        }
    }
    __syncthreads();
    int b1 = sh_b1, rem1 = sh_rem1;
    for (int i = tid; i < 256; i += 1024) hist[i] = 0;
    __syncthreads();
    for (int i = tid; i < C; i += 1024) {
        unsigned kk = g_candk[i];
        if ((int)((kk >> 8) & 255) == b1) atomicAdd(&hist[kk & 255], 1);
    }
    __syncthreads();
    if (tid == 0) {
        int cum = 0;
        for (int b = 255; b >= 0; b--) {
            int h = hist[b];
            if (cum + h >= rem1) { sh_b0 = b; sh_needed = rem1 - cum; break; }
            cum += h;
        }
    }
    __syncthreads();
    unsigned lo_t = ((unsigned)b1 << 8) | (unsigned)sh_b0;
    int needed = sh_needed;
    for (int i = tid; i < C; i += 1024) {
        unsigned lo = g_candk[i] & 0xFFFFu;
        int v = g_candv[i];
        if (lo > lo_t) {
            int p = atomicAdd(&g_selcnt, 1);
            g_list[lout][p] = v;
        } else if (lo < lo_t) {
            g_alive[v] = 0;
        } else {
            int p = atomicAdd(&sh_tc, 1);
            if (p < TCAP) tiebuf[p] = v;
        }
    }
    __syncthreads();
    int T = sh_tc;
    if (T <= needed) {
        for (int i = tid; i < C; i += 1024) {
            if ((g_candk[i] & 0xFFFFu) == lo_t) {
                int p = atomicAdd(&g_selcnt, 1);
                g_list[lout][p] = g_candv[i];
            }
        }
    } else if (T <= TCAP) {
        for (int j = tid; j < T; j += 1024) {
            int vj = tiebuf[j];
            int r = 0;
            for (int q = 0; q < T; q++) r += (tiebuf[q] < vj);
            if (r < needed) {
                int p = atomicAdd(&g_selcnt, 1);
                g_list[lout][p] = vj;
            } else g_alive[vj] = 0;
        }
    } else {
        for (int i = tid; i < C; i += 1024) {
            if ((g_candk[i] & 0xFFFFu) != lo_t) continue;
            int vi = g_candv[i];
            int r = 0;
            for (int q = 0; q < C; q++)
                if ((g_candk[q] & 0xFFFFu) == lo_t && g_candv[q] < vi) r++;
            if (r < needed) {
                int p = atomicAdd(&g_selcnt, 1);
                g_list[lout][p] = vi;
            } else g_alive[vi] = 0;
        }
    }
}
__global__ __launch_bounds__(128) void k_pool(int b, int lout, int kb, float invk, int doZero) {
    __shared__ float sth[64];
    __shared__ int sv[64];
    int c = threadIdx.x;
    int base = blockIdx.x * 64;
    int lim = min(64, kb - base);
    if (c < 64 && c < lim) {
        int v = g_list[lout][base + c];
        float th = tanhf(g_score[v]);
        sth[c] = th; sv[c] = v; g_th[v] = th;
        if (doZero) { g_deg_in[v] = 0; g_deg_out[v] = 0; }
    }
    if (doZero) {
        for (int i = blockIdx.x * blockDim.x + c; i < HB; i += gridDim.x * blockDim.x) g_hist[i] = 0;
        if (base == 0 && c == 0) {
            g_total = 0; g_selcnt = 0; g_candcnt = 0;
            if (b == 0) g_e1n = 0; else g_e2n = 0;
        }
    }
    __syncthreads();
    float msum = 0.f, mmax = __int_as_float(0xff800000);
    for (int j = 0; j < lim; j++) {
        float val = g_hrelu[sv[j] * 128 + c] * sth[j];
        msum += val;
        mmax = fmaxf(mmax, val);
    }
    atomicAdd(&g_mean[c], msum * invk);
    atomicMaxF(&g_bmax[b * 128 + c], mmax);
}
__global__ __launch_bounds__(1024) void k_mlp(const float* __restrict__ seq,
                                              const float* __restrict__ W1, const float* __restrict__ b1,
                                              const float* __restrict__ W2, const float* __restrict__ b2,
                                              const float* __restrict__ W3, const float* __restrict__ b3,
                                              float* __restrict__ out) {
    __shared__ float fin[1280];
    __shared__ float red[1024];
    __shared__ float f1[256];
    __shared__ float f2[128];
    int t = threadIdx.x;
    for (int i = t; i < 1280; i += 1024) {
        float v;
        if (i < 128)      v = g_mean[i];
        else if (i < 256) v = g_bmax[i - 128] + g_bmax[128 + (i - 128)] + g_bmax[256 + (i - 128)];
        else              v = seq[i - 256];
        fin[i] = v;
    }
    __syncthreads();
    {
        int o = t & 255, part = t >> 8;
        float acc = 0.f;
        int k0 = part * 320;
        for (int k = k0; k < k0 + 320; k++) acc = fmaf(fin[k], W1[k * 256 + o], acc);
        red[t] = acc;
    }
    __syncthreads();
    if (t < 256) {
        float s = red[t] + red[t + 256] + red[t + 512] + red[t + 768] + b1[t];
        f1[t] = fmaxf(s, 0.f);
    }
    __syncthreads();
    if (t < 128) {
        float acc = b2[t];
        for (int k = 0; k < 256; k++) acc = fmaf(f1[k], W2[k * 128 + t], acc);
        f2[t] = fmaxf(acc, 0.f);
    }
    __syncthreads();
#pragma unroll
    for (int r = 0; r < 2; r++) {
        int o = t + r * 1024;
        float acc = b3[o];
        for (int k = 0; k < 128; k++) acc = fmaf(f2[k], W3[k * 2048 + o], acc);
        out[o] = acc;
    }
}

extern "C" void kernel_launch(void* const* d_in, const int* in_sizes, int n_in,
                              void* d_out, int out_size) {
    const float* feat = (const float*)d_in[0];
    const float* seq  = (const float*)d_in[1];
    const int*   src  = (const int*)d_in[2];
    const int*   dst  = (const int*)d_in[3];
    const float* cW[3] = {(const float*)d_in[6],  (const float*)d_in[10], (const float*)d_in[14]};
    const float* cb[3] = {(const float*)d_in[7],  (const float*)d_in[11], (const float*)d_in[15]};
    const float* sW[3] = {(const float*)d_in[8],  (const float*)d_in[12], (const float*)d_in[16]};
    const float* sb[3] = {(const float*)d_in[9],  (const float*)d_in[13], (const float*)d_in[17]};
    const float* l1W = (const float*)d_in[18];
    const float* l1b = (const float*)d_in[19];
    const float* l2W = (const float*)d_in[20];
    const float* l2b = (const float*)d_in[21];
    const float* l3W = (const float*)d_in[22];
    const float* l3b = (const float*)d_in[23];
    float* out = (float*)d_out;

    const int nAv[3] = {50000, 25000, 12500};
    const int kbv[3] = {25000, 12500, 6250};
    const int EGRID = (EE + 255) / 256;

    k_init0<<<(HB + 255) / 256, 256>>>();
    for (int b = 0; b < 3; b++) {
        int nA = nAv[b], kb = kbv[b];
        int lin = b & 1, lout = 1 - lin;
        int gemmG = (nA + 63) / 64;
        k_deg_gemm<<<gemmG + EGRID, 256>>>(b == 0 ? feat : (const float*)0, cW[b],
                                           lin, nA, b > 0, src, dst, b, gemmG);
        k_alloc<<<(NN + 255) / 256, 256>>>();
        k_scatter<<<EGRID, 256>>>(src, dst, b);
        k_spmm_conv<<<(nA + 7) / 8, 256>>>(cb[b], sW[b], lin, nA);
        k_spmm_score<<<(nA + 7) / 8, 256>>>(sb[b], lin, nA);
        k_pick<<<1, 1024>>>(kb);
        k_cand<<<(nA + 255) / 256, 256>>>(lin, lout, nA);
        k_finish<<<1, 1024>>>(lout, kb);
        k_pool<<<(kb + 63) / 64, 128>>>(b, lout, kb, 1.0f / (float)kb, b < 2);
    }
    k_mlp<<<1, 1024>>>(seq, l1W, l1b, l2W, l2b, l3W, l3b, out);
}

// round 11
// speedup vs baseline: 1.1595x; 1.0708x over previous
// SAGNetworkHierarchical GB300 kernel, round 11.
// R10: 370.7us. This round: (a) CSR built once and reused across all 3
// blocks (dead nodes carry ns=0/hs2=0 so masked-graph terms vanish),
// (b) pool(b-1) fused as a third role into front(b) (gemm|degree|pool),
// th computed from score inside gemm. Zeroing moved into cand/finish.
#include <cuda_runtime.h>
#include <math.h>

#define NN 50000
#define EE 800000
#define HB 65536
#define TCAP 6144
#define EGRID 3125   // ceil(EE/256)

__device__ float    g_hs[NN * 128];
__device__ float    g_hrelu[NN * 128];
__device__ float    g_hs2[NN];
__device__ float    g_score[NN];
__device__ unsigned g_key[NN];
__device__ int      g_deg_in[NN];
__device__ int      g_deg_out[NN];
__device__ int      g_deg0[NN];
__device__ int      g_rowptr[NN];
__device__ int      g_csr[EE];
__device__ int      g_ord[EE];
__device__ int      g_alive[NN];
__device__ int      g_list[2][NN];
__device__ float    g_ns[NN];
__device__ float    g_nd[NN];
__device__ float    g_mean[128];
__device__ float    g_bmax[3 * 128];
__device__ int      g_total;
__device__ int      g_hist[HB];
__device__ int      g_bucketHi;
__device__ int      g_cntAbove;
__device__ int      g_selcnt;
__device__ int      g_candcnt;
__device__ unsigned g_candk[NN];
__device__ int      g_candv[NN];

__device__ __forceinline__ unsigned okey(float f) {
    unsigned u = __float_as_uint(f);
    return (u & 0x80000000u) ? ~u : (u | 0x80000000u);
}
__device__ __forceinline__ void atomicMaxF(float* a, float v) {
    if (v >= 0.f) atomicMax((int*)a, __float_as_int(v));
    else          atomicMin((unsigned*)a, __float_as_uint(v));
}

__global__ void k_init0() {
    int i = blockIdx.x * blockDim.x + threadIdx.x;
    if (i < NN) { g_alive[i] = 1; g_list[0][i] = i; g_deg_in[i] = 0; g_deg_out[i] = 0; }
    if (i < HB) g_hist[i] = 0;
    if (i < 128) g_mean[i] = 0.f;
    if (i < 3 * 128) g_bmax[i] = __int_as_float(0xff800000);
    if (i == 0) { g_total = 0; g_selcnt = 0; g_candcnt = 0; }
}
// front(b): [0,gemmG) gemm role; [gemmG, gemmG+EGRID) degree role;
// [gemmG+EGRID, +poolG) pool(b-1) role. All roles mutually independent.
__global__ __launch_bounds__(256, 3) void k_front(
    const float* __restrict__ x, const float* __restrict__ W,
    int lin, int nA, int useTh,
    const int* __restrict__ src, const int* __restrict__ dst, int mode,
    int gemmG, int poolBm, float invk) {
    __shared__ float xs[64][128];
    __shared__ int rid[64];
    int tid = threadIdx.x;
    if (blockIdx.x >= gemmG + EGRID) {
        // ---- pool role for previous block: nodes = g_list[lin][0..nA) ----
        __shared__ float sth[64];
        __shared__ int sv[64];
        int pb = blockIdx.x - gemmG - EGRID;
        int base = pb * 64;
        int lim = min(64, nA - base);
        if (tid < 64 && tid < lim) {
            int v = g_list[lin][base + tid];
            sv[tid] = v;
            sth[tid] = tanhf(g_score[v]);
        }
        __syncthreads();
        int c = tid & 127, half = tid >> 7;
        int j0 = half * 32, j1 = min(lim, j0 + 32);
        float msum = 0.f, mmax = __int_as_float(0xff800000);
        for (int j = j0; j < j1; j++) {
            float val = g_hrelu[sv[j] * 128 + c] * sth[j];
            msum += val;
            mmax = fmaxf(mmax, val);
        }
        if (j0 < lim) {
            atomicAdd(&g_mean[c], msum * invk);
            atomicMaxF(&g_bmax[poolBm * 128 + c], mmax);
        }
        return;
    }
    if (blockIdx.x >= gemmG) {
        // ---- degree role over ORIGINAL edge list ----
        int i = (blockIdx.x - gemmG) * 256 + tid;
        if (i >= EE) return;
        int s = src[i], d = dst[i];
        if (mode == 0) {
            atomicAdd(&g_deg_out[s], 1);
            g_ord[i] = atomicAdd(&g_deg_in[d], 1);
        } else if (g_alive[s] && g_alive[d]) {
            atomicAdd(&g_deg_out[s], 1);
            atomicAdd(&g_deg_in[d], 1);
        }
        return;
    }
    // ---- gemm role: hs[v] = (x[v] @ W) * (useTh ? tanh(score[v]) : 1) ----
    const float* xp = x ? x : (const float*)g_hrelu;
    if (tid < 64) {
        int r = blockIdx.x * 64 + tid;
        rid[tid] = (r < nA) ? g_list[lin][r] : -1;
    }
    __syncthreads();
    for (int i = tid; i < 2048; i += 256) {
        int row = i >> 5, c4 = i & 31;
        int v = rid[row];
        float4 xv = make_float4(0.f, 0.f, 0.f, 0.f);
        if (v >= 0) xv = *(const float4*)&xp[v * 128 + c4 * 4];
        *(float4*)&xs[row][c4 * 4] = xv;
    }
    __syncthreads();
    int cg = tid & 31, rg = tid >> 5;
    float4 acc[8];
#pragma unroll
    for (int j = 0; j < 8; j++) acc[j] = make_float4(0.f, 0.f, 0.f, 0.f);
#pragma unroll 8
    for (int k0 = 0; k0 < 128; k0 += 4) {
        float4 w0 = *(const float4*)&W[(k0 + 0) * 128 + cg * 4];
        float4 w1 = *(const float4*)&W[(k0 + 1) * 128 + cg * 4];
        float4 w2 = *(const float4*)&W[(k0 + 2) * 128 + cg * 4];
        float4 w3 = *(const float4*)&W[(k0 + 3) * 128 + cg * 4];
#pragma unroll
        for (int j = 0; j < 8; j++) {
            float4 xv = *(const float4*)&xs[rg * 8 + j][k0];
            acc[j].x = fmaf(xv.x, w0.x, acc[j].x); acc[j].y = fmaf(xv.x, w0.y, acc[j].y);
            acc[j].z = fmaf(xv.x, w0.z, acc[j].z); acc[j].w = fmaf(xv.x, w0.w, acc[j].w);
            acc[j].x = fmaf(xv.y, w1.x, acc[j].x); acc[j].y = fmaf(xv.y, w1.y, acc[j].y);
            acc[j].z = fmaf(xv.y, w1.z, acc[j].z); acc[j].w = fmaf(xv.y, w1.w, acc[j].w);
            acc[j].x = fmaf(xv.z, w2.x, acc[j].x); acc[j].y = fmaf(xv.z, w2.y, acc[j].y);
            acc[j].z = fmaf(xv.z, w2.z, acc[j].z); acc[j].w = fmaf(xv.z, w2.w, acc[j].w);
            acc[j].x = fmaf(xv.w, w3.x, acc[j].x); acc[j].y = fmaf(xv.w, w3.y, acc[j].y);
            acc[j].z = fmaf(xv.w, w3.z, acc[j].z); acc[j].w = fmaf(xv.w, w3.w, acc[j].w);
        }
    }
#pragma unroll
    for (int j = 0; j < 8; j++) {
        int v = rid[rg * 8 + j];
        if (v >= 0) {
            float s = useTh ? tanhf(g_score[v]) : 1.0f;  // score from prev block
            float4 o = make_float4(acc[j].x * s, acc[j].y * s, acc[j].z * s, acc[j].w * s);
            *(float4*)&g_hs[v * 128 + cg * 4] = o;
        }
    }
}
// mode0: rowptr scan + deg0 + ns/nd; else: ns/nd only for alive
__global__ void k_alloc(int mode) {
    int i = blockIdx.x * blockDim.x + threadIdx.x;
    int lane = threadIdx.x & 31;
    int alive = (i < NN) ? g_alive[i] : 0;
    int d = alive ? g_deg_in[i] : 0;
    if (mode == 0) {
        int x = d;
#pragma unroll
        for (int o = 1; o < 32; o <<= 1) { int t = __shfl_up_sync(~0u, x, o); if (lane >= o) x += t; }
        int base;
        if (lane == 31) base = atomicAdd(&g_total, x);
        base = __shfl_sync(~0u, base, 31);
        if (i < NN) { g_rowptr[i] = base + x - d; g_deg0[i] = d; }
    }
    if (alive) {
        g_ns[i] = 1.0f / sqrtf(fmaxf((float)g_deg_out[i], 1.0f));
        g_nd[i] = 1.0f / sqrtf(fmaxf((float)d, 1.0f));
    }
}
__global__ void k_scatter(const int* __restrict__ src, const int* __restrict__ dst) {
    int i = blockIdx.x * blockDim.x + threadIdx.x;
    if (i >= EE) return;
    g_csr[g_rowptr[dst[i]] + g_ord[i]] = src[i];
}
// gather over ORIGINAL row; dead neighbors have ns=0 -> skipped
__global__ __launch_bounds__(256) void k_spmm_conv(const float* __restrict__ cb,
                                                   const float* __restrict__ sW,
                                                   int lin, int nA) {
    int gw = (blockIdx.x * blockDim.x + threadIdx.x) >> 5;
    int lane = threadIdx.x & 31;
    if (gw >= nA) return;
    int v = g_list[lin][gw];
    int s = g_rowptr[v];
    int nb = g_deg0[v];
    float a0 = 0.f, a1 = 0.f, a2 = 0.f, a3 = 0.f;
    for (int i0 = 0; i0 < nb; i0 += 32) {
        int u32 = 0; float ns32 = 0.f;
        if (i0 + lane < nb) { u32 = g_csr[s + i0 + lane]; ns32 = g_ns[u32]; }
        int lim = min(32, nb - i0);
        for (int j = 0; j < lim; j++) {
            float nsu = __shfl_sync(~0u, ns32, j);
            int u = __shfl_sync(~0u, u32, j);
            if (nsu != 0.f) {   // warp-uniform: dead source skipped
                float4 h = *(const float4*)&g_hs[u * 128 + lane * 4];
                a0 = fmaf(h.x, nsu, a0); a1 = fmaf(h.y, nsu, a1);
                a2 = fmaf(h.z, nsu, a2); a3 = fmaf(h.w, nsu, a3);
            }
        }
    }
    float ndv = g_nd[v];
    float4 b = *(const float4*)&cb[lane * 4];
    float4 hr;
    hr.x = fmaxf(fmaf(a0, ndv, b.x), 0.f);
    hr.y = fmaxf(fmaf(a1, ndv, b.y), 0.f);
    hr.z = fmaxf(fmaf(a2, ndv, b.z), 0.f);
    hr.w = fmaxf(fmaf(a3, ndv, b.w), 0.f);
    *(float4*)&g_hrelu[v * 128 + lane * 4] = hr;
    float4 w = *(const float4*)&sW[lane * 4];
    float sd = hr.x * w.x + hr.y * w.y + hr.z * w.z + hr.w * w.w;
#pragma unroll
    for (int o = 16; o; o >>= 1) sd += __shfl_down_sync(~0u, sd, o);
    if (lane == 0) g_hs2[v] = sd * g_ns[v];
}
// dead u contribute hs2=0 -> plain sum over original row
__global__ __launch_bounds__(256) void k_spmm_score(const float* __restrict__ sb,
                                                    int lin, int nA) {
    int gw = (blockIdx.x * blockDim.x + threadIdx.x) >> 5;
    int lane = threadIdx.x & 31;
    if (gw >= nA) return;
    int v = g_list[lin][gw];
    int s = g_rowptr[v], e = s + g_deg0[v];
    float sum = 0.f;
    for (int i = s + lane; i < e; i += 32) sum += g_hs2[g_csr[i]];
#pragma unroll
    for (int o = 16; o; o >>= 1) sum += __shfl_down_sync(~0u, sum, o);
    if (lane == 0) {
        float sc = fmaf(sum, g_nd[v], sb[0]);
        g_score[v] = sc;
        unsigned kk = okey(sc);
        g_key[v] = kk;
        atomicAdd(&g_hist[kk >> 16], 1);
    }
}
__global__ __launch_bounds__(1024) void k_pick(int k) {
    __shared__ int A[1024];
    int t = threadIdx.x;
    const int4* h4 = (const int4*)g_hist;
    int base4 = t * 16;
    int s = 0;
#pragma unroll
    for (int b = 0; b < 16; b++) {
        int4 v = h4[base4 + b];
        s += v.x + v.y + v.z + v.w;
    }
    A[t] = s;
    __syncthreads();
    for (int off = 1; off < 1024; off <<= 1) {
        int w = A[t] + ((t + off < 1024) ? A[t + off] : 0);
        __syncthreads();
        A[t] = w;
        __syncthreads();
    }
    int above = A[t] - s;
    if (above < k && above + s >= k) {
        int cum = above;
        int base = t * 64;
        for (int b = 63; b >= 0; b--) {
            int h = g_hist[base + b];
            if (cum + h >= k) { g_bucketHi = base + b; g_cntAbove = cum; break; }
            cum += h;
        }
    }
}
// split + kill (ns/hs2 zeroed for dead; deg zeroed for survivors) + hist zero
__global__ void k_cand(int lin, int lout, int nA) {
    int gid = blockIdx.x * blockDim.x + threadIdx.x;
    for (int j = gid; j < HB; j += gridDim.x * blockDim.x) g_hist[j] = 0;
    int i = gid;
    int bh = g_bucketHi;
    int v = -1; unsigned key = 0; int hi = -1;
    if (i < nA) { v = g_list[lin][i]; key = g_key[v]; hi = (int)(key >> 16); }
    bool gt = (i < nA) && (hi > bh);
    bool eq = (i < nA) && (hi == bh);
    int lane = threadIdx.x & 31;
    unsigned m = __ballot_sync(~0u, gt);
    if (m) {
        int ldr = __ffs(m) - 1; int base;
        if (lane == ldr) base = atomicAdd(&g_selcnt, __popc(m));
        base = __shfl_sync(~0u, base, ldr);
        if (gt) {
            g_list[lout][base + __popc(m & ((1u << lane) - 1))] = v;
            g_deg_in[v] = 0; g_deg_out[v] = 0;
        }
    }
    unsigned m2 = __ballot_sync(~0u, eq);
    if (m2) {
        int ldr = __ffs(m2) - 1; int base;
        if (lane == ldr) base = atomicAdd(&g_candcnt, __popc(m2));
        base = __shfl_sync(~0u, base, ldr);
        if (eq) {
            int p = base + __popc(m2 & ((1u << lane) - 1));
            g_candk[p] = key; g_candv[p] = v;
        }
    }
    if (i < nA && !gt && !eq) { g_alive[v] = 0; g_ns[v] = 0.f; g_hs2[v] = 0.f; }
}
__global__ __launch_bounds__(1024) void k_finish(int lout, int k) {
    __shared__ int hist[256];
    __shared__ int sh_b1, sh_rem1, sh_b0, sh_needed, sh_tc;
    __shared__ int tiebuf[TCAP];
    int tid = threadIdx.x;
    int C = g_candcnt;
    int kp = k - g_cntAbove;
    for (int i = tid; i < 256; i += 1024) hist[i] = 0;
    if (tid == 0) sh_tc = 0;
    __syncthreads();
    for (int i = tid; i < C; i += 1024) atomicAdd(&hist[(g_candk[i] >> 8) & 255], 1);
    __syncthreads();
    if (tid == 0) {
        int cum = 0;
        for (int b = 255; b >= 0; b--) {
            int h = hist[b];
            if (cum + h >= kp) { sh_b1 = b; sh_rem1 = kp - cum; break; }
            cum += h;
        }
    }
    __syncthreads();
    int b1 = sh_b1, rem1 = sh_rem1;
    for (int i = tid; i < 256; i += 1024) hist[i] = 0;
    __syncthreads();
    for (int i = tid; i < C; i += 1024) {
        unsigned kk = g_candk[i];
        if ((int)((kk >> 8) & 255) == b1) atomicAdd(&hist[kk & 255], 1);
    }
    __syncthreads();
    if (tid == 0) {
        int cum = 0;
        for (int b = 255; b >= 0; b--) {
            int h = hist[b];
            if (cum + h >= rem1) { sh_b0 = b; sh_needed = rem1 - cum; break; }
            cum += h;
        }
    }
    __syncthreads();
    unsigned lo_t = ((unsigned)b1 << 8) | (unsigned)sh_b0;
    int needed = sh_needed;
    for (int i = tid; i < C; i += 1024) {
        unsigned lo = g_candk[i] & 0xFFFFu;
        int v = g_candv[i];
        if (lo > lo_t) {
            int p = atomicAdd(&g_selcnt, 1);
            g_list[lout][p] = v;
            g_deg_in[v] = 0; g_deg_out[v] = 0;
        } else if (lo < lo_t) {
            g_alive[v] = 0; g_ns[v] = 0.f; g_hs2[v] = 0.f;
        } else {
            int p = atomicAdd(&sh_tc, 1);
            if (p < TCAP) tiebuf[p] = v;
        }
    }
    __syncthreads();
    int T = sh_tc;
    if (T <= needed) {
        for (int i = tid; i < C; i += 1024) {
            if ((g_candk[i] & 0xFFFFu) == lo_t) {
                int v = g_candv[i];
                int p = atomicAdd(&g_selcnt, 1);
                g_list[lout][p] = v;
                g_deg_in[v] = 0; g_deg_out[v] = 0;
            }
        }
    } else if (T <= TCAP) {
        for (int j = tid; j < T; j += 1024) {
            int vj = tiebuf[j];
            int r = 0;
            for (int q = 0; q < T; q++) r += (tiebuf[q] < vj);
            if (r < needed) {
                int p = atomicAdd(&g_selcnt, 1);
                g_list[lout][p] = vj;
                g_deg_in[vj] = 0; g_deg_out[vj] = 0;
            } else { g_alive[vj] = 0; g_ns[vj] = 0.f; g_hs2[vj] = 0.f; }
        }
    } else {
        for (int i = tid; i < C; i += 1024) {
            if ((g_candk[i] & 0xFFFFu) != lo_t) continue;
            int vi = g_candv[i];
            int r = 0;
            for (int q = 0; q < C; q++)
                if ((g_candk[q] & 0xFFFFu) == lo_t && g_candv[q] < vi) r++;
            if (r < needed) {
                int p = atomicAdd(&g_selcnt, 1);
                g_list[lout][p] = vi;
                g_deg_in[vi] = 0; g_deg_out[vi] = 0;
            } else { g_alive[vi] = 0; g_ns[vi] = 0.f; g_hs2[vi] = 0.f; }
        }
    }
    __syncthreads();
    if (tid == 0) { g_selcnt = 0; g_candcnt = 0; g_total = 0; }
}
// standalone pool for the LAST block (feeds mlp directly)
__global__ __launch_bounds__(128) void k_pool(int bm, int lst, int kb, float invk) {
    __shared__ float sth[64];
    __shared__ int sv[64];
    int c = threadIdx.x;
    int base = blockIdx.x * 64;
    int lim = min(64, kb - base);
    if (c < 64 && c < lim) {
        int v = g_list[lst][base + c];
        sv[c] = v;
        sth[c] = tanhf(g_score[v]);
    }
    __syncthreads();
    float msum = 0.f, mmax = __int_as_float(0xff800000);
    for (int j = 0; j < lim; j++) {
        float val = g_hrelu[sv[j] * 128 + c] * sth[j];
        msum += val;
        mmax = fmaxf(mmax, val);
    }
    atomicAdd(&g_mean[c], msum * invk);
    atomicMaxF(&g_bmax[bm * 128 + c], mmax);
}
__global__ __launch_bounds__(1024) void k_mlp(const float* __restrict__ seq,
                                              const float* __restrict__ W1, const float* __restrict__ b1,
                                              const float* __restrict__ W2, const float* __restrict__ b2,
                                              const float* __restrict__ W3, const float* __restrict__ b3,
                                              float* __restrict__ out) {
    __shared__ float fin[1280];
    __shared__ float red[1024];
    __shared__ float f1[256];
    __shared__ float f2[128];
    int t = threadIdx.x;
    for (int i = t; i < 1280; i += 1024) {
        float v;
        if (i < 128)      v = g_mean[i];
        else if (i < 256) v = g_bmax[i - 128] + g_bmax[128 + (i - 128)] + g_bmax[256 + (i - 128)];
        else              v = seq[i - 256];
        fin[i] = v;
    }
    __syncthreads();
    {
        int o = t & 255, part = t >> 8;
        float acc = 0.f;
        int k0 = part * 320;
        for (int k = k0; k < k0 + 320; k++) acc = fmaf(fin[k], W1[k * 256 + o], acc);
        red[t] = acc;
    }
    __syncthreads();
    if (t < 256) {
        float s = red[t] + red[t + 256] + red[t + 512] + red[t + 768] + b1[t];
        f1[t] = fmaxf(s, 0.f);
    }
    __syncthreads();
    if (t < 128) {
        float acc = b2[t];
        for (int k = 0; k < 256; k++) acc = fmaf(f1[k], W2[k * 128 + t], acc);
        f2[t] = fmaxf(acc, 0.f);
    }
    __syncthreads();
#pragma unroll
    for (int r = 0; r < 2; r++) {
        int o = t + r * 1024;
        float acc = b3[o];
        for (int k = 0; k < 128; k++) acc = fmaf(f2[k], W3[k * 2048 + o], acc);
        out[o] = acc;
    }
}

extern "C" void kernel_launch(void* const* d_in, const int* in_sizes, int n_in,
                              void* d_out, int out_size) {
    const float* feat = (const float*)d_in[0];
    const float* seq  = (const float*)d_in[1];
    const int*   src  = (const int*)d_in[2];
    const int*   dst  = (const int*)d_in[3];
    const float* cW[3] = {(const float*)d_in[6],  (const float*)d_in[10], (const float*)d_in[14]};
    const float* cb[3] = {(const float*)d_in[7],  (const float*)d_in[11], (const float*)d_in[15]};
    const float* sW[3] = {(const float*)d_in[8],  (const float*)d_in[12], (const float*)d_in[16]};
    const float* sb[3] = {(const float*)d_in[9],  (const float*)d_in[13], (const float*)d_in[17]};
    const float* l1W = (const float*)d_in[18];
    const float* l1b = (const float*)d_in[19];
    const float* l2W = (const float*)d_in[20];
    const float* l2b = (const float*)d_in[21];
    const float* l3W = (const float*)d_in[22];
    const float* l3b = (const float*)d_in[23];
    float* out = (float*)d_out;

    const int nAv[3] = {50000, 25000, 12500};
    const int kbv[3] = {25000, 12500, 6250};

    k_init0<<<(HB + 255) / 256, 256>>>();
    for (int b = 0; b < 3; b++) {
        int nA = nAv[b], kb = kbv[b];
        int lin = b & 1, lout = 1 - lin;
        int gemmG = (nA + 63) / 64;
        int poolG = (b > 0) ? gemmG : 0;       // pool(b-1) has nA nodes
        k_front<<<gemmG + EGRID + poolG, 256>>>(
            b == 0 ? feat : (const float*)0, cW[b], lin, nA, b > 0,
            src, dst, b, gemmG, b - 1, 1.0f / (float)nA);
        k_alloc<<<(NN + 255) / 256, 256>>>(b);
        if (b == 0) k_scatter<<<EGRID, 256>>>(src, dst);
        k_spmm_conv<<<(nA + 7) / 8, 256>>>(cb[b], sW[b], lin, nA);
        k_spmm_score<<<(nA + 7) / 8, 256>>>(sb[b], lin, nA);
        k_pick<<<1, 1024>>>(kb);
        k_cand<<<(nA + 255) / 256, 256>>>(lin, lout, nA);
        k_finish<<<1, 1024>>>(lout, kb);
    }
    k_pool<<<(6250 + 63) / 64, 128>>>(2, 1, 6250, 1.0f / 6250.0f);
    k_mlp<<<1, 1024>>>(seq, l1W, l1b, l2W, l2b, l3W, l3b, out);
}

// round 12
// speedup vs baseline: 1.2231x; 1.0549x over previous
// SAGNetworkHierarchical GB300 kernel, round 12.
// R11: 346.2us. This round: (a) drop k_alloc for b1/b2 + g_ns/g_nd arrays;
// norms computed on the fly from degrees, dead nodes flagged deg_out=-1;
// (b) g_hs stored as fp16 (halves the SpMM gather's L2 traffic; fp32 accum).
#include <cuda_runtime.h>
#include <cuda_fp16.h>
#include <math.h>

#define NN 50000
#define EE 800000
#define HB 65536
#define TCAP 6144
#define EGRID 3125   // ceil(EE/256)

__device__ __half    g_hs[NN * 128];
__device__ float     g_hrelu[NN * 128];
__device__ float     g_hs2[NN];
__device__ float     g_score[NN];
__device__ unsigned  g_key[NN];
__device__ int       g_deg_in[NN];
__device__ int       g_deg_out[NN];
__device__ int       g_deg0[NN];
__device__ int       g_rowptr[NN];
__device__ int       g_csr[EE];
__device__ int       g_ord[EE];
__device__ int       g_alive[NN];
__device__ int       g_list[2][NN];
__device__ float     g_mean[128];
__device__ float     g_bmax[3 * 128];
__device__ int       g_total;
__device__ int       g_hist[HB];
__device__ int       g_bucketHi;
__device__ int       g_cntAbove;
__device__ int       g_selcnt;
__device__ int       g_candcnt;
__device__ unsigned  g_candk[NN];
__device__ int       g_candv[NN];

__device__ __forceinline__ unsigned okey(float f) {
    unsigned u = __float_as_uint(f);
    return (u & 0x80000000u) ? ~u : (u | 0x80000000u);
}
__device__ __forceinline__ void atomicMaxF(float* a, float v) {
    if (v >= 0.f) atomicMax((int*)a, __float_as_int(v));
    else          atomicMin((unsigned*)a, __float_as_uint(v));
}
__device__ __forceinline__ float invs(int d) {   // 1/sqrt(max(d,1))
    return 1.0f / sqrtf((float)(d > 0 ? d : 1));
}

__global__ void k_init0() {
    int i = blockIdx.x * blockDim.x + threadIdx.x;
    if (i < NN) { g_alive[i] = 1; g_list[0][i] = i; g_deg_in[i] = 0; g_deg_out[i] = 0; }
    if (i < HB) g_hist[i] = 0;
    if (i < 128) g_mean[i] = 0.f;
    if (i < 3 * 128) g_bmax[i] = __int_as_float(0xff800000);
    if (i == 0) { g_total = 0; g_selcnt = 0; g_candcnt = 0; }
}
// front(b): [0,gemmG) gemm role; [gemmG, gemmG+EGRID) degree role;
// [gemmG+EGRID, +poolG) pool(b-1) role. Roles mutually independent.
__global__ __launch_bounds__(256, 3) void k_front(
    const float* __restrict__ x, const float* __restrict__ W,
    int lin, int nA, int useTh,
    const int* __restrict__ src, const int* __restrict__ dst, int mode,
    int gemmG, int poolBm, float invk) {
    __shared__ float xs[64][128];
    __shared__ int rid[64];
    int tid = threadIdx.x;
    if (blockIdx.x >= gemmG + EGRID) {
        // ---- pool role for previous block ----
        __shared__ float sth[64];
        __shared__ int sv[64];
        int pb = blockIdx.x - gemmG - EGRID;
        int base = pb * 64;
        int lim = min(64, nA - base);
        if (tid < 64 && tid < lim) {
            int v = g_list[lin][base + tid];
            sv[tid] = v;
            sth[tid] = tanhf(g_score[v]);
        }
        __syncthreads();
        int c = tid & 127, half = tid >> 7;
        int j0 = half * 32, j1 = min(lim, j0 + 32);
        float msum = 0.f, mmax = __int_as_float(0xff800000);
        for (int j = j0; j < j1; j++) {
            float val = g_hrelu[sv[j] * 128 + c] * sth[j];
            msum += val;
            mmax = fmaxf(mmax, val);
        }
        if (j0 < lim) {
            atomicAdd(&g_mean[c], msum * invk);
            atomicMaxF(&g_bmax[poolBm * 128 + c], mmax);
        }
        return;
    }
    if (blockIdx.x >= gemmG) {
        // ---- degree role over ORIGINAL edge list ----
        int i = (blockIdx.x - gemmG) * 256 + tid;
        if (i >= EE) return;
        int s = src[i], d = dst[i];
        if (mode == 0) {
            atomicAdd(&g_deg_out[s], 1);
            g_ord[i] = atomicAdd(&g_deg_in[d], 1);
        } else if (g_alive[s] && g_alive[d]) {
            atomicAdd(&g_deg_out[s], 1);
            atomicAdd(&g_deg_in[d], 1);
        }
        return;
    }
    // ---- gemm role: hs[v] = fp16( (x[v] @ W) * (useTh ? tanh(score[v]) : 1) )
    const float* xp = x ? x : (const float*)g_hrelu;
    if (tid < 64) {
        int r = blockIdx.x * 64 + tid;
        rid[tid] = (r < nA) ? g_list[lin][r] : -1;
    }
    __syncthreads();
    for (int i = tid; i < 2048; i += 256) {
        int row = i >> 5, c4 = i & 31;
        int v = rid[row];
        float4 xv = make_float4(0.f, 0.f, 0.f, 0.f);
        if (v >= 0) xv = *(const float4*)&xp[v * 128 + c4 * 4];
        *(float4*)&xs[row][c4 * 4] = xv;
    }
    __syncthreads();
    int cg = tid & 31, rg = tid >> 5;
    float4 acc[8];
#pragma unroll
    for (int j = 0; j < 8; j++) acc[j] = make_float4(0.f, 0.f, 0.f, 0.f);
#pragma unroll 8
    for (int k0 = 0; k0 < 128; k0 += 4) {
        float4 w0 = *(const float4*)&W[(k0 + 0) * 128 + cg * 4];
        float4 w1 = *(const float4*)&W[(k0 + 1) * 128 + cg * 4];
        float4 w2 = *(const float4*)&W[(k0 + 2) * 128 + cg * 4];
        float4 w3 = *(const float4*)&W[(k0 + 3) * 128 + cg * 4];
#pragma unroll
        for (int j = 0; j < 8; j++) {
            float4 xv = *(const float4*)&xs[rg * 8 + j][k0];
            acc[j].x = fmaf(xv.x, w0.x, acc[j].x); acc[j].y = fmaf(xv.x, w0.y, acc[j].y);
            acc[j].z = fmaf(xv.x, w0.z, acc[j].z); acc[j].w = fmaf(xv.x, w0.w, acc[j].w);
            acc[j].x = fmaf(xv.y, w1.x, acc[j].x); acc[j].y = fmaf(xv.y, w1.y, acc[j].y);
            acc[j].z = fmaf(xv.y, w1.z, acc[j].z); acc[j].w = fmaf(xv.y, w1.w, acc[j].w);
            acc[j].x = fmaf(xv.z, w2.x, acc[j].x); acc[j].y = fmaf(xv.z, w2.y, acc[j].y);
            acc[j].z = fmaf(xv.z, w2.z, acc[j].z); acc[j].w = fmaf(xv.z, w2.w, acc[j].w);
            acc[j].x = fmaf(xv.w, w3.x, acc[j].x); acc[j].y = fmaf(xv.w, w3.y, acc[j].y);
            acc[j].z = fmaf(xv.w, w3.z, acc[j].z); acc[j].w = fmaf(xv.w, w3.w, acc[j].w);
        }
    }
#pragma unroll
    for (int j = 0; j < 8; j++) {
        int v = rid[rg * 8 + j];
        if (v >= 0) {
            float s = useTh ? tanhf(g_score[v]) : 1.0f;  // score from prev block
            __half2 h01 = __floats2half2_rn(acc[j].x * s, acc[j].y * s);
            __half2 h23 = __floats2half2_rn(acc[j].z * s, acc[j].w * s);
            uint2 o;
            o.x = *(unsigned*)&h01; o.y = *(unsigned*)&h23;
            *(uint2*)&g_hs[v * 128 + cg * 4] = o;
        }
    }
}
// b0 only: rowptr exclusive scan + frozen degree copy
__global__ void k_alloc() {
    int i = blockIdx.x * blockDim.x + threadIdx.x;
    int lane = threadIdx.x & 31;
    int d = (i < NN) ? g_deg_in[i] : 0;
    int x = d;
#pragma unroll
    for (int o = 1; o < 32; o <<= 1) { int t = __shfl_up_sync(~0u, x, o); if (lane >= o) x += t; }
    int base;
    if (lane == 31) base = atomicAdd(&g_total, x);
    base = __shfl_sync(~0u, base, 31);
    if (i < NN) { g_rowptr[i] = base + x - d; g_deg0[i] = d; }
}
__global__ void k_scatter(const int* __restrict__ src, const int* __restrict__ dst) {
    int i = blockIdx.x * blockDim.x + threadIdx.x;
    if (i >= EE) return;
    g_csr[g_rowptr[dst[i]] + g_ord[i]] = src[i];
}
// gather over original row; dead u flagged deg_out[u] = -1 -> skipped
__global__ __launch_bounds__(256) void k_spmm_conv(const float* __restrict__ cb,
                                                   const float* __restrict__ sW,
                                                   int lin, int nA) {
    int gw = (blockIdx.x * blockDim.x + threadIdx.x) >> 5;
    int lane = threadIdx.x & 31;
    if (gw >= nA) return;
    int v = g_list[lin][gw];
    int s = g_rowptr[v];
    int nb = g_deg0[v];
    float a0 = 0.f, a1 = 0.f, a2 = 0.f, a3 = 0.f;
    for (int i0 = 0; i0 < nb; i0 += 32) {
        int u32 = 0; float ns32 = 0.f;
        if (i0 + lane < nb) {
            u32 = g_csr[s + i0 + lane];
            int du = g_deg_out[u32];
            ns32 = (du < 0) ? 0.f : invs(du);
        }
        int lim = min(32, nb - i0);
        for (int j = 0; j < lim; j++) {
            float nsu = __shfl_sync(~0u, ns32, j);
            int u = __shfl_sync(~0u, u32, j);
            if (nsu != 0.f) {
                uint2 p = *(const uint2*)&g_hs[u * 128 + lane * 4];
                float2 f01 = __half22float2(*(__half2*)&p.x);
                float2 f23 = __half22float2(*(__half2*)&p.y);
                a0 = fmaf(f01.x, nsu, a0); a1 = fmaf(f01.y, nsu, a1);
                a2 = fmaf(f23.x, nsu, a2); a3 = fmaf(f23.y, nsu, a3);
            }
        }
    }
    float ndv = invs(g_deg_in[v]);
    float4 b = *(const float4*)&cb[lane * 4];
    float4 hr;
    hr.x = fmaxf(fmaf(a0, ndv, b.x), 0.f);
    hr.y = fmaxf(fmaf(a1, ndv, b.y), 0.f);
    hr.z = fmaxf(fmaf(a2, ndv, b.z), 0.f);
    hr.w = fmaxf(fmaf(a3, ndv, b.w), 0.f);
    *(float4*)&g_hrelu[v * 128 + lane * 4] = hr;
    float4 w = *(const float4*)&sW[lane * 4];
    float sd = hr.x * w.x + hr.y * w.y + hr.z * w.z + hr.w * w.w;
#pragma unroll
    for (int o = 16; o; o >>= 1) sd += __shfl_down_sync(~0u, sd, o);
    if (lane == 0) g_hs2[v] = sd * invs(g_deg_out[v]);   // v alive -> deg >= 0
}
// dead u contribute hs2=0 -> plain sum over original row
__global__ __launch_bounds__(256) void k_spmm_score(const float* __restrict__ sb,
                                                    int lin, int nA) {
    int gw = (blockIdx.x * blockDim.x + threadIdx.x) >> 5;
    int lane = threadIdx.x & 31;
    if (gw >= nA) return;
    int v = g_list[lin][gw];
    int s = g_rowptr[v], e = s + g_deg0[v];
    float sum = 0.f;
    for (int i = s + lane; i < e; i += 32) sum += g_hs2[g_csr[i]];
#pragma unroll
    for (int o = 16; o; o >>= 1) sum += __shfl_down_sync(~0u, sum, o);
    if (lane == 0) {
        float sc = fmaf(sum, invs(g_deg_in[v]), sb[0]);
        g_score[v] = sc;
        unsigned kk = okey(sc);
        g_key[v] = kk;
        atomicAdd(&g_hist[kk >> 16], 1);
    }
}
__global__ __launch_bounds__(1024) void k_pick(int k) {
    __shared__ int A[1024];
    int t = threadIdx.x;
    const int4* h4 = (const int4*)g_hist;
    int base4 = t * 16;
    int s = 0;
#pragma unroll
    for (int b = 0; b < 16; b++) {
        int4 v = h4[base4 + b];
        s += v.x + v.y + v.z + v.w;
    }
    A[t] = s;
    __syncthreads();
    for (int off = 1; off < 1024; off <<= 1) {
        int w = A[t] + ((t + off < 1024) ? A[t + off] : 0);
        __syncthreads();
        A[t] = w;
        __syncthreads();
    }
    int above = A[t] - s;
    if (above < k && above + s >= k) {
        int cum = above;
        int base = t * 64;
        for (int b = 63; b >= 0; b--) {
            int h = g_hist[base + b];
            if (cum + h >= k) { g_bucketHi = base + b; g_cntAbove = cum; break; }
            cum += h;
        }
    }
}
__global__ void k_cand(int lin, int lout, int nA) {
    int gid = blockIdx.x * blockDim.x + threadIdx.x;
    for (int j = gid; j < HB; j += gridDim.x * blockDim.x) g_hist[j] = 0;
    int i = gid;
    int bh = g_bucketHi;
    int v = -1; unsigned key = 0; int hi = -1;
    if (i < nA) { v = g_list[lin][i]; key = g_key[v]; hi = (int)(key >> 16); }
    bool gt = (i < nA) && (hi > bh);
    bool eq = (i < nA) && (hi == bh);
    int lane = threadIdx.x & 31;
    unsigned m = __ballot_sync(~0u, gt);
    if (m) {
        int ldr = __ffs(m) - 1; int base;
        if (lane == ldr) base = atomicAdd(&g_selcnt, __popc(m));
        base = __shfl_sync(~0u, base, ldr);
        if (gt) {
            g_list[lout][base + __popc(m & ((1u << lane) - 1))] = v;
            g_deg_in[v] = 0; g_deg_out[v] = 0;
        }
    }
    unsigned m2 = __ballot_sync(~0u, eq);
    if (m2) {
        int ldr = __ffs(m2) - 1; int base;
        if (lane == ldr) base = atomicAdd(&g_candcnt, __popc(m2));
        base = __shfl_sync(~0u, base, ldr);
        if (eq) {
            int p = base + __popc(m2 & ((1u << lane) - 1));
            g_candk[p] = key; g_candv[p] = v;
        }
    }
    if (i < nA && !gt && !eq) { g_alive[v] = 0; g_deg_out[v] = -1; g_hs2[v] = 0.f; }
}
__global__ __launch_bounds__(1024) void k_finish(int lout, int k) {
    __shared__ int hist[256];
    __shared__ int sh_b1, sh_rem1, sh_b0, sh_needed, sh_tc;
    __shared__ int tiebuf[TCAP];
    int tid = threadIdx.x;
    int C = g_candcnt;
    int kp = k - g_cntAbove;
    for (int i = tid; i < 256; i += 1024) hist[i] = 0;
    if (tid == 0) sh_tc = 0;
    __syncthreads();
    for (int i = tid; i < C; i += 1024) atomicAdd(&hist[(g_candk[i] >> 8) & 255], 1);
    __syncthreads();
    if (tid == 0) {
        int cum = 0;
        for (int b = 255; b >= 0; b--) {
            int h = hist[b];
            if (cum + h >= kp) { sh_b1 = b; sh_rem1 = kp - cum; break; }
            cum += h;
        }
    }
    __syncthreads();
    int b1 = sh_b1, rem1 = sh_rem1;
    for (int i = tid; i < 256; i += 1024) hist[i] = 0;
    __syncthreads();
    for (int i = tid; i < C; i += 1024) {
        unsigned kk = g_candk[i];
        if ((int)((kk >> 8) & 255) == b1) atomicAdd(&hist[kk & 255], 1);
    }
    __syncthreads();
    if (tid == 0) {
        int cum = 0;
        for (int b = 255; b >= 0; b--) {
            int h = hist[b];
            if (cum + h >= rem1) { sh_b0 = b; sh_needed = rem1 - cum; break; }
            cum += h;
        }
    }
    __syncthreads();
    unsigned lo_t = ((unsigned)b1 << 8) | (unsigned)sh_b0;
    int needed = sh_needed;
    for (int i = tid; i < C; i += 1024) {
        unsigned lo = g_candk[i] & 0xFFFFu;
        int v = g_candv[i];
        if (lo > lo_t) {
            int p = atomicAdd(&g_selcnt, 1);
            g_list[lout][p] = v;
            g_deg_in[v] = 0; g_deg_out[v] = 0;
        } else if (lo < lo_t) {
            g_alive[v] = 0; g_deg_out[v] = -1; g_hs2[v] = 0.f;
        } else {
            int p = atomicAdd(&sh_tc, 1);
            if (p < TCAP) tiebuf[p] = v;
        }
    }
    __syncthreads();
    int T = sh_tc;
    if (T <= needed) {
        for (int i = tid; i < C; i += 1024) {
            if ((g_candk[i] & 0xFFFFu) == lo_t) {
                int v = g_candv[i];
                int p = atomicAdd(&g_selcnt, 1);
                g_list[lout][p] = v;
                g_deg_in[v] = 0; g_deg_out[v] = 0;
            }
        }
    } else if (T <= TCAP) {
        for (int j = tid; j < T; j += 1024) {
            int vj = tiebuf[j];
            int r = 0;
            for (int q = 0; q < T; q++) r += (tiebuf[q] < vj);
            if (r < needed) {
                int p = atomicAdd(&g_selcnt, 1);
                g_list[lout][p] = vj;
                g_deg_in[vj] = 0; g_deg_out[vj] = 0;
            } else { g_alive[vj] = 0; g_deg_out[vj] = -1; g_hs2[vj] = 0.f; }
        }
    } else {
        for (int i = tid; i < C; i += 1024) {
            if ((g_candk[i] & 0xFFFFu) != lo_t) continue;
            int vi = g_candv[i];
            int r = 0;
            for (int q = 0; q < C; q++)
                if ((g_candk[q] & 0xFFFFu) == lo_t && g_candv[q] < vi) r++;
            if (r < needed) {
                int p = atomicAdd(&g_selcnt, 1);
                g_list[lout][p] = vi;
                g_deg_in[vi] = 0; g_deg_out[vi] = 0;
            } else { g_alive[vi] = 0; g_deg_out[vi] = -1; g_hs2[vi] = 0.f; }
        }
    }
    __syncthreads();
    if (tid == 0) { g_selcnt = 0; g_candcnt = 0; g_total = 0; }
}
// standalone pool for the LAST block
__global__ __launch_bounds__(128) void k_pool(int bm, int lst, int kb, float invk) {
    __shared__ float sth[64];
    __shared__ int sv[64];
    int c = threadIdx.x;
    int base = blockIdx.x * 64;
    int lim = min(64, kb - base);
    if (c < 64 && c < lim) {
        int v = g_list[lst][base + c];
        sv[c] = v;
        sth[c] = tanhf(g_score[v]);
    }
    __syncthreads();
    float msum = 0.f, mmax = __int_as_float(0xff800000);
    for (int j = 0; j < lim; j++) {
        float val = g_hrelu[sv[j] * 128 + c] * sth[j];
        msum += val;
        mmax = fmaxf(mmax, val);
    }
    atomicAdd(&g_mean[c], msum * invk);
    atomicMaxF(&g_bmax[bm * 128 + c], mmax);
}
__global__ __launch_bounds__(1024) void k_mlp(const float* __restrict__ seq,
                                              const float* __restrict__ W1, const float* __restrict__ b1,
                                              const float* __restrict__ W2, const float* __restrict__ b2,
                                              const float* __restrict__ W3, const float* __restrict__ b3,
                                              float* __restrict__ out) {
    __shared__ float fin[1280];
    __shared__ float red[1024];
    __shared__ float f1[256];
    __shared__ float f2[128];
    int t = threadIdx.x;
    for (int i = t; i < 1280; i += 1024) {
        float v;
        if (i < 128)      v = g_mean[i];
        else if (i < 256) v = g_bmax[i - 128] + g_bmax[128 + (i - 128)] + g_bmax[256 + (i - 128)];
        else              v = seq[i - 256];
        fin[i] = v;
    }
    __syncthreads();
    {
        int o = t & 255, part = t >> 8;
        float acc = 0.f;
        int k0 = part * 320;
        for (int k = k0; k < k0 + 320; k++) acc = fmaf(fin[k], W1[k * 256 + o], acc);
        red[t] = acc;
    }
    __syncthreads();
    if (t < 256) {
        float s = red[t] + red[t + 256] + red[t + 512] + red[t + 768] + b1[t];
        f1[t] = fmaxf(s, 0.f);
    }
    __syncthreads();
    if (t < 128) {
        float acc = b2[t];
        for (int k = 0; k < 256; k++) acc = fmaf(f1[k], W2[k * 128 + t], acc);
        f2[t] = fmaxf(acc, 0.f);
    }
    __syncthreads();
#pragma unroll
    for (int r = 0; r < 2; r++) {
        int o = t + r * 1024;
        float acc = b3[o];
        for (int k = 0; k < 128; k++) acc = fmaf(f2[k], W3[k * 2048 + o], acc);
        out[o] = acc;
    }
}

extern "C" void kernel_launch(void* const* d_in, const int* in_sizes, int n_in,
                              void* d_out, int out_size) {
    const float* feat = (const float*)d_in[0];
    const float* seq  = (const float*)d_in[1];
    const int*   src  = (const int*)d_in[2];
    const int*   dst  = (const int*)d_in[3];
    const float* cW[3] = {(const float*)d_in[6],  (const float*)d_in[10], (const float*)d_in[14]};
    const float* cb[3] = {(const float*)d_in[7],  (const float*)d_in[11], (const float*)d_in[15]};
    const float* sW[3] = {(const float*)d_in[8],  (const float*)d_in[12], (const float*)d_in[16]};
    const float* sb[3] = {(const float*)d_in[9],  (const float*)d_in[13], (const float*)d_in[17]};
    const float* l1W = (const float*)d_in[18];
    const float* l1b = (const float*)d_in[19];
    const float* l2W = (const float*)d_in[20];
    const float* l2b = (const float*)d_in[21];
    const float* l3W = (const float*)d_in[22];
    const float* l3b = (const float*)d_in[23];
    float* out = (float*)d_out;

    const int nAv[3] = {50000, 25000, 12500};
    const int kbv[3] = {25000, 12500, 6250};

    k_init0<<<(HB + 255) / 256, 256>>>();
    for (int b = 0; b < 3; b++) {
        int nA = nAv[b], kb = kbv[b];
        int lin = b & 1, lout = 1 - lin;
        int gemmG = (nA + 63) / 64;
        int poolG = (b > 0) ? gemmG : 0;
        k_front<<<gemmG + EGRID + poolG, 256>>>(
            b == 0 ? feat : (const float*)0, cW[b], lin, nA, b > 0,
            src, dst, b, gemmG, b - 1, 1.0f / (float)nA);
        if (b == 0) {
            k_alloc<<<(NN + 255) / 256, 256>>>();
            k_scatter<<<EGRID, 256>>>(src, dst);
        }
        k_spmm_conv<<<(nA + 7) / 8, 256>>>(cb[b], sW[b], lin, nA);
        k_spmm_score<<<(nA + 7) / 8, 256>>>(sb[b], lin, nA);
        k_pick<<<1, 1024>>>(kb);
        k_cand<<<(nA + 255) / 256, 256>>>(lin, lout, nA);
        k_finish<<<1, 1024>>>(lout, kb);
    }
    k_pool<<<(6250 + 63) / 64, 128>>>(2, 1, 6250, 1.0f / 6250.0f);
    k_mlp<<<1, 1024>>>(seq, l1W, l1b, l2W, l2b, l3W, l3b, out);
}